// round 3
// baseline (speedup 1.0000x reference)
#include <cuda_runtime.h>
#include <math.h>

typedef unsigned long long ull;

#define N_BOX 400
#define C_CLS 151
#define D_X   4096
#define E_EMB 200
#define H_DIM 512
#define P_POS 128
#define K_REP  4424
#define K_REP2 4224
#define TAIL_W 328          /* E_EMB + P_POS */
#define FNEG_INF (-3.402823466e38f)
#define NSPLIT 4
#define KSPLIT 1106
#define MM_NONE (1<<30)

// ---------------- scratch ----------------
__device__ float  g_tail[N_BOX * TAIL_W];
__device__ float  g_part[NSPLIT * N_BOX * H_DIM];
__device__ float  g_h1  [N_BOX * H_DIM];
__device__ float  g_fcb [N_BOX * H_DIM];
__device__ float  g_tab [C_CLS * H_DIM];
__device__ float  g_scores[C_CLS * N_BOX];     // column-major: [c][r]
__device__ float4 g_rowinit[N_BOX];            // (m1, c1, m2, c2)
__device__ float  g_boxT[C_CLS * N_BOX * 4];   // boxT[c][r] float4
__device__ int    g_labels[N_BOX];

// ---------------- f32x2 helpers ----------------
__device__ __forceinline__ void ffma2(ull& d, ull a, ull b) {
    asm("fma.rn.f32x2 %0, %1, %2, %0;" : "+l"(d) : "l"(a), "l"(b));
}
__device__ __forceinline__ ull pack2(float lo, float hi) {
    ull r;
    asm("mov.b64 %0, {%1, %2};" : "=l"(r) : "f"(lo), "f"(hi));
    return r;
}
__device__ __forceinline__ void unpack2(ull v, float& lo, float& hi) {
    asm("mov.b64 {%0, %1}, %2;" : "=f"(lo), "=f"(hi) : "l"(v));
}

__device__ __forceinline__ float warp_max(float v) {
    #pragma unroll
    for (int o = 16; o; o >>= 1) v = fmaxf(v, __shfl_xor_sync(0xffffffffu, v, o));
    return v;
}
__device__ __forceinline__ float warp_sum(float v) {
    #pragma unroll
    for (int o = 16; o; o >>= 1) v += __shfl_xor_sync(0xffffffffu, v, o);
    return v;
}

// ---------------- boxes transpose ----------------
__global__ __launch_bounds__(160) void transpose_boxes(const float* __restrict__ boxes)
{
    int r = blockIdx.x, c = threadIdx.x;
    if (c < C_CLS) {
        float4 v = ((const float4*)boxes)[(size_t)r * C_CLS + c];
        ((float4*)g_boxT)[(size_t)c * N_BOX + r] = v;
    }
}

// ---------------- prep: obj_embed + pos_embed -> g_tail ----------------
__global__ __launch_bounds__(256) void prep_kernel(
    const float* __restrict__ logits,
    const float* __restrict__ pos, const float* __restrict__ obj_embed_w,
    const float* __restrict__ w_pos1, const float* __restrict__ b_pos1,
    const float* __restrict__ bn_g, const float* __restrict__ bn_b,
    const float* __restrict__ bn_m, const float* __restrict__ bn_v,
    const float* __restrict__ w_pos2, const float* __restrict__ b_pos2)
{
    int row = blockIdx.x, tid = threadIdx.x;
    __shared__ float sp[C_CLS];
    __shared__ float sh[32];
    __shared__ float sred[8];

    float lv = (tid < C_CLS) ? logits[row * C_CLS + tid] : FNEG_INF;
    float m = warp_max(lv);
    if ((tid & 31) == 0) sred[tid >> 5] = m;
    __syncthreads();
    float bm = sred[0];
    #pragma unroll
    for (int i = 1; i < 8; i++) bm = fmaxf(bm, sred[i]);
    float e = (tid < C_CLS) ? expf(lv - bm) : 0.f;
    float s = warp_sum(e);
    __syncthreads();
    if ((tid & 31) == 0) sred[tid >> 5] = s;
    __syncthreads();
    float bs = 0.f;
    #pragma unroll
    for (int i = 0; i < 8; i++) bs += sred[i];
    if (tid < C_CLS) sp[tid] = e / bs;

    if (tid < 32) {
        float acc = b_pos1[tid];
        #pragma unroll
        for (int k = 0; k < 9; k++) acc += pos[row * 9 + k] * w_pos1[k * 32 + tid];
        acc = (acc - bn_m[tid]) / sqrtf(bn_v[tid] + 1e-5f) * bn_g[tid] + bn_b[tid];
        sh[tid] = acc;
    }
    __syncthreads();

    if (tid < E_EMB) {
        float acc = 0.f;
        for (int k = 0; k < C_CLS; k++) acc += sp[k] * obj_embed_w[k * E_EMB + tid];
        g_tail[row * TAIL_W + tid] = acc;
    }
    if (tid < P_POS) {
        float acc = b_pos2[tid];
        #pragma unroll
        for (int k = 0; k < 32; k++) acc += sh[k] * w_pos2[k * P_POS + tid];
        g_tail[row * TAIL_W + E_EMB + tid] = fmaxf(acc, 0.f);
    }
}

// ---------------- h1 split-K GEMM with f32x2 ----------------
// BM=16,BN=128,BK=16, 128 thr, 4x4/thread (rows paired)
__global__ __launch_bounds__(128) void h1_splitk_kernel(
    const float* __restrict__ x, const float* __restrict__ wlin)
{
    __shared__ __align__(16) float As[16][18];
    __shared__ __align__(16) float Bs[16][128];
    int tid = threadIdx.x;
    int tx = tid & 31, ty = tid >> 5;
    int row0 = blockIdx.y * 16;
    int col0 = blockIdx.x * 128;
    int s    = blockIdx.z;
    int kbeg = s * KSPLIT, kend = kbeg + KSPLIT;

    ull acc[2][4];
    #pragma unroll
    for (int p = 0; p < 2; p++)
        #pragma unroll
        for (int c = 0; c < 4; c++) acc[p][c] = 0ull;

    for (int k0 = kbeg; k0 < kend; k0 += 16) {
        #pragma unroll
        for (int i = 0; i < 2; i++) {
            int l = tid * 2 + i;
            int m = l >> 4, k = l & 15;
            int gr = row0 + m, gk = k0 + k;
            float v = 0.f;
            if (gk < kend)
                v = (gk < D_X) ? x[(size_t)gr * D_X + gk]
                               : g_tail[gr * TAIL_W + (gk - D_X)];
            As[k][m] = v;
        }
        #pragma unroll
        for (int i = 0; i < 4; i++) {
            int f = tid + i * 128;
            int k = f >> 5, n = (f & 31) << 2;
            int gk = k0 + k;
            float4 v = make_float4(0.f, 0.f, 0.f, 0.f);
            if (gk < kend) v = *(const float4*)(wlin + (size_t)gk * H_DIM + col0 + n);
            *(float4*)&Bs[k][n] = v;
        }
        __syncthreads();
        #pragma unroll
        for (int k = 0; k < 16; k++) {
            ull a01 = *(const ull*)&As[k][ty * 4];
            ull a23 = *(const ull*)&As[k][ty * 4 + 2];
            float4 bv = *(const float4*)&Bs[k][tx * 4];
            ull b0 = pack2(bv.x, bv.x), b1 = pack2(bv.y, bv.y);
            ull b2 = pack2(bv.z, bv.z), b3 = pack2(bv.w, bv.w);
            ffma2(acc[0][0], a01, b0); ffma2(acc[0][1], a01, b1);
            ffma2(acc[0][2], a01, b2); ffma2(acc[0][3], a01, b3);
            ffma2(acc[1][0], a23, b0); ffma2(acc[1][1], a23, b1);
            ffma2(acc[1][2], a23, b2); ffma2(acc[1][3], a23, b3);
        }
        __syncthreads();
    }
    float* outp = g_part + (size_t)s * N_BOX * H_DIM;
    #pragma unroll
    for (int p = 0; p < 2; p++) {
        int gr0 = row0 + ty * 4 + p * 2;
        #pragma unroll
        for (int c = 0; c < 4; c++) {
            float lo, hi;
            unpack2(acc[p][c], lo, hi);
            int gn = col0 + tx * 4 + c;
            outp[(size_t)gr0 * H_DIM + gn] = lo;
            outp[(size_t)(gr0 + 1) * H_DIM + gn] = hi;
        }
    }
}

// ---------------- reduce partials + bias -> g_h1 ----------------
__global__ __launch_bounds__(512) void reduce_h1_kernel(const float* __restrict__ b_lin)
{
    int r = blockIdx.x, c = threadIdx.x;
    size_t o = (size_t)r * H_DIM + c;
    float v = b_lin[c];
    #pragma unroll
    for (int s = 0; s < NSPLIT; s++) v += g_part[(size_t)s * N_BOX * H_DIM + o];
    g_h1[o] = v;
}

// ---------------- dists SGEMM (scalar, small) ----------------
__global__ __launch_bounds__(128) void sgemm_kernel(
    const float* __restrict__ A, int lda,
    const float* __restrict__ B, int ldb,
    float* __restrict__ C, int ldc,
    int M, int N, int K,
    const float* __restrict__ bias)
{
    __shared__ float As[16][17];
    __shared__ float Bs[16][128];
    int tid = threadIdx.x;
    int tx = tid & 31, ty = tid >> 5;
    int row0 = blockIdx.y * 16;
    int col0 = blockIdx.x * 128;
    float acc[4][4];
    #pragma unroll
    for (int i = 0; i < 4; i++)
        #pragma unroll
        for (int j = 0; j < 4; j++) acc[i][j] = 0.f;

    for (int k0 = 0; k0 < K; k0 += 16) {
        #pragma unroll
        for (int i = 0; i < 2; i++) {
            int l = tid * 2 + i;
            int m = l >> 4, k = l & 15;
            int gr = row0 + m, gk = k0 + k;
            As[k][m] = (gr < M && gk < K) ? A[(size_t)gr * lda + gk] : 0.f;
        }
        #pragma unroll
        for (int i = 0; i < 4; i++) {
            int f = tid + i * 128;
            int k = f >> 5, n = (f & 31) << 2;
            int gk = k0 + k, gn = col0 + n;
            float4 v = make_float4(0.f, 0.f, 0.f, 0.f);
            if (gk < K) {
                float t0 = (gn + 0 < N) ? B[(size_t)gk * ldb + gn + 0] : 0.f;
                float t1 = (gn + 1 < N) ? B[(size_t)gk * ldb + gn + 1] : 0.f;
                float t2 = (gn + 2 < N) ? B[(size_t)gk * ldb + gn + 2] : 0.f;
                float t3 = (gn + 3 < N) ? B[(size_t)gk * ldb + gn + 3] : 0.f;
                v = make_float4(t0, t1, t2, t3);
            }
            *(float4*)&Bs[k][n] = v;
        }
        __syncthreads();
        #pragma unroll
        for (int k = 0; k < 16; k++) {
            float a0 = As[k][ty * 4 + 0];
            float a1 = As[k][ty * 4 + 1];
            float a2 = As[k][ty * 4 + 2];
            float a3 = As[k][ty * 4 + 3];
            float4 bv = *(float4*)&Bs[k][tx * 4];
            acc[0][0] += a0 * bv.x; acc[0][1] += a0 * bv.y; acc[0][2] += a0 * bv.z; acc[0][3] += a0 * bv.w;
            acc[1][0] += a1 * bv.x; acc[1][1] += a1 * bv.y; acc[1][2] += a1 * bv.z; acc[1][3] += a1 * bv.w;
            acc[2][0] += a2 * bv.x; acc[2][1] += a2 * bv.y; acc[2][2] += a2 * bv.z; acc[2][3] += a2 * bv.w;
            acc[3][0] += a3 * bv.x; acc[3][1] += a3 * bv.y; acc[3][2] += a3 * bv.z; acc[3][3] += a3 * bv.w;
        }
        __syncthreads();
    }
    #pragma unroll
    for (int i = 0; i < 4; i++) {
        int gr = row0 + ty * 4 + i;
        if (gr >= M) continue;
        #pragma unroll
        for (int j = 0; j < 4; j++) {
            int gn = col0 + tx * 4 + j;
            if (gn >= N) continue;
            C[(size_t)gr * ldc + gn] = acc[i][j] + bias[gn];
        }
    }
}

// ---------------- scores: softmax (col-major) + per-row top-2 init ----------------
__global__ __launch_bounds__(256) void scores_kernel(const float* __restrict__ obj_dists)
{
    int row = blockIdx.x, tid = threadIdx.x;
    __shared__ float sred[8];
    __shared__ float4 stop[8];

    float lv = (tid < C_CLS) ? obj_dists[row * C_CLS + tid] : FNEG_INF;
    float m = warp_max(lv);
    if ((tid & 31) == 0) sred[tid >> 5] = m;
    __syncthreads();
    float bm = sred[0];
    #pragma unroll
    for (int i = 1; i < 8; i++) bm = fmaxf(bm, sred[i]);
    float e = (tid < C_CLS) ? expf(lv - bm) : 0.f;
    float s = warp_sum(e);
    __syncthreads();
    if ((tid & 31) == 0) sred[tid >> 5] = s;
    __syncthreads();
    float bs = 0.f;
    #pragma unroll
    for (int i = 0; i < 8; i++) bs += sred[i];

    float v = (tid == 0) ? -1.f : e / bs;
    if (tid < C_CLS) g_scores[tid * N_BOX + row] = v;

    // top-2 over positive entries (cols 1..150)
    float tv = (tid > 0 && tid < C_CLS) ? v : -1e30f;
    float m1 = tv, m2 = -1e30f;
    int c1 = tid, c2 = 0x7fff;
    #pragma unroll
    for (int o = 16; o; o >>= 1) {
        float om1 = __shfl_xor_sync(0xffffffffu, m1, o);
        float om2 = __shfl_xor_sync(0xffffffffu, m2, o);
        int   oc1 = __shfl_xor_sync(0xffffffffu, c1, o);
        int   oc2 = __shfl_xor_sync(0xffffffffu, c2, o);
        if (om1 > m1 || (om1 == m1 && oc1 < c1)) { m2 = m1; c2 = c1; m1 = om1; c1 = oc1; }
        else if (om1 > m2 || (om1 == m2 && oc1 < c2)) { m2 = om1; c2 = oc1; }
        if (om2 > m2 || (om2 == m2 && oc2 < c2)) { m2 = om2; c2 = oc2; }
    }
    if ((tid & 31) == 0) stop[tid >> 5] = make_float4(m1, __int_as_float(c1), m2, __int_as_float(c2));
    __syncthreads();
    if (tid == 0) {
        float4 a = stop[0];
        float rm1 = a.x, rm2 = a.z;
        int rc1 = __float_as_int(a.y), rc2 = __float_as_int(a.w);
        for (int w = 1; w < 8; w++) {
            float4 b = stop[w];
            float wm1 = b.x, wm2 = b.z;
            int wc1 = __float_as_int(b.y), wc2 = __float_as_int(b.w);
            if (wm1 > rm1 || (wm1 == rm1 && wc1 < rc1)) { rm2 = rm1; rc2 = rc1; rm1 = wm1; rc1 = wc1; }
            else if (wm1 > rm2 || (wm1 == rm2 && wc1 < rc2)) { rm2 = wm1; rc2 = wc1; }
            if (wm2 > rm2 || (wm2 == rm2 && wc2 < rc2)) { rm2 = wm2; rc2 = wc2; }
        }
        g_rowinit[row] = make_float4(rm1, __int_as_float(rc1), rm2, __int_as_float(rc2));
    }
}

// ============== fused: block0 greedy, blocks 1..140 fcb/tab GEMM tiles ==============
#define FCB_BLOCKS 100   /* 25 mt x 4 nt */
#define TAB_BLOCKS 40    /* 10 mt x 4 nt */
#define FUSED_GRID (1 + FCB_BLOCKS + TAB_BLOCKS)

__device__ __forceinline__ void gemm16x128_f32x2(
    const float* __restrict__ A, int lda, int mode,   // mode0: composite [x | pos_embed]
    const float* __restrict__ x,
    const float* __restrict__ B,                      // ldb = 512
    float* __restrict__ Cg,
    int M, int K, const float* __restrict__ bias,
    int mt, int nt, float (*As)[18], float (*Bs)[128])
{
    int tid = threadIdx.x;
    int tx = tid & 31, ty = tid >> 5;
    int row0 = mt * 16, col0 = nt * 128;
    ull acc[2][4];
    #pragma unroll
    for (int p = 0; p < 2; p++)
        #pragma unroll
        for (int c = 0; c < 4; c++) acc[p][c] = 0ull;

    for (int k0 = 0; k0 < K; k0 += 16) {
        #pragma unroll
        for (int i = 0; i < 2; i++) {
            int l = tid * 2 + i;
            int m = l >> 4, k = l & 15;
            int gr = row0 + m, gk = k0 + k;
            float v = 0.f;
            if (gr < M && gk < K) {
                if (mode == 0)
                    v = (gk < D_X) ? x[(size_t)gr * D_X + gk]
                                   : g_tail[gr * TAIL_W + E_EMB + (gk - D_X)];
                else
                    v = A[(size_t)gr * lda + gk];
            }
            As[k][m] = v;
        }
        #pragma unroll
        for (int i = 0; i < 4; i++) {
            int f = tid + i * 128;
            int k = f >> 5, n = (f & 31) << 2;
            int gk = k0 + k;
            float4 v = make_float4(0.f, 0.f, 0.f, 0.f);
            if (gk < K) v = *(const float4*)(B + (size_t)gk * H_DIM + col0 + n);
            *(float4*)&Bs[k][n] = v;
        }
        __syncthreads();
        #pragma unroll
        for (int k = 0; k < 16; k++) {
            ull a01 = *(const ull*)&As[k][ty * 4];
            ull a23 = *(const ull*)&As[k][ty * 4 + 2];
            float4 bv = *(const float4*)&Bs[k][tx * 4];
            ull b0 = pack2(bv.x, bv.x), b1 = pack2(bv.y, bv.y);
            ull b2 = pack2(bv.z, bv.z), b3 = pack2(bv.w, bv.w);
            ffma2(acc[0][0], a01, b0); ffma2(acc[0][1], a01, b1);
            ffma2(acc[0][2], a01, b2); ffma2(acc[0][3], a01, b3);
            ffma2(acc[1][0], a23, b0); ffma2(acc[1][1], a23, b1);
            ffma2(acc[1][2], a23, b2); ffma2(acc[1][3], a23, b3);
        }
        __syncthreads();
    }
    #pragma unroll
    for (int p = 0; p < 2; p++) {
        int gr0 = row0 + ty * 4 + p * 2;
        #pragma unroll
        for (int c = 0; c < 4; c++) {
            float lo, hi;
            unpack2(acc[p][c], lo, hi);
            int gn = col0 + tx * 4 + c;
            float b = bias ? bias[gn] : 0.f;
            if (gr0 < M)     Cg[(size_t)gr0 * H_DIM + gn] = lo + b;
            if (gr0 + 1 < M) Cg[(size_t)(gr0 + 1) * H_DIM + gn] = hi + b;
        }
    }
}

__global__ __launch_bounds__(128, 1) void fused_kernel(
    const float* __restrict__ x,
    const float* __restrict__ w_fc, const float* __restrict__ b_fc,
    const float* __restrict__ objw2)
{
    __shared__ __align__(16) float As[16][18];
    __shared__ __align__(16) float Bs[16][128];
    __shared__ ull s_sel[N_BOX + 1];

    int bid = blockIdx.x;
    int tid = threadIdx.x;

    if (bid >= 1 && bid < 1 + FCB_BLOCKS) {
        int bi = bid - 1;
        gemm16x128_f32x2(0, 0, 0, x, w_fc, g_fcb, N_BOX, K_REP2, b_fc,
                         bi >> 2, bi & 3, As, Bs);
        return;
    }
    if (bid >= 1 + FCB_BLOCKS) {
        int bj = bid - 1 - FCB_BLOCKS;
        gemm16x128_f32x2(objw2, E_EMB, 1, x, w_fc + (size_t)K_REP2 * H_DIM, g_tab,
                         C_CLS, E_EMB, 0, bj >> 2, bj & 3, As, Bs);
        return;
    }

    // ================= block 0: greedy NMS, 128 threads, 4 rows/thread =================
    int lane = tid & 31;

    for (int i = tid; i <= N_BOX; i += 128) s_sel[i] = 0ull;

    float m1[4], m2[4];
    int   c1[4], c2[4], mmv[4];
    float scl[4 * C_CLS];           // thread-local row copies

    #pragma unroll
    for (int j = 0; j < 4; j++) {
        int r = tid + j * 128;
        if (r < N_BOX) {
            float4 ri = g_rowinit[r];
            m1[j] = ri.x; c1[j] = __float_as_int(ri.y);
            m2[j] = ri.z; c2[j] = __float_as_int(ri.w);
            mmv[j] = MM_NONE;
            g_labels[r] = 0;
            for (int c = 0; c < C_CLS; c++)
                scl[j * C_CLS + c] = g_scores[c * N_BOX + r];
        } else {
            c1[j] = -1; c2[j] = -1; mmv[j] = MM_NONE;
            m1[j] = 0.f; m2[j] = 0.f;
        }
    }

    // per-row selection pack
    #define ROWPACK(j, r, out) do {                                          \
        float _v; int _sc;                                                   \
        if (c1[j] >= 0) { _v = m1[j]; _sc = c1[j]; }                         \
        else if (mmv[j] < MM_NONE) { _v = 0.f; _sc = mmv[j]; }               \
        else { _v = -1.f; _sc = 0; }                                         \
        out = ((ull)__float_as_uint(_v + 2.f) << 17)                         \
            | ((ull)(511 - (r)) << 8) | (ull)_sc;                            \
    } while (0)

    // initial selection
    {
        ull p = 0ull;
        #pragma unroll
        for (int j = 0; j < 4; j++) {
            int r = tid + j * 128;
            if (r < N_BOX) { ull q; ROWPACK(j, r, q); if (q > p) p = q; }
        }
        #pragma unroll
        for (int o = 16; o; o >>= 1) {
            ull q = __shfl_xor_sync(0xffffffffu, p, o);
            if (q > p) p = q;
        }
        if (lane == 0 && p) atomicMax(&s_sel[0], p);
        __syncthreads();
    }

    for (int t = 0; t < N_BOX; t++) {
        ull sel = s_sel[t];
        int box = 511 - (int)((sel >> 8) & 0x1FF);
        int cls = (int)(sel & 0xFF);

        const float4* bt = (const float4*)g_boxT + (size_t)cls * N_BOX;
        float4 sb = bt[box];
        float4 bbj[4];
        #pragma unroll
        for (int j = 0; j < 4; j++) {
            int r = tid + j * 128;
            if (r < N_BOX) bbj[j] = bt[r];
        }
        float sarea = (sb.z - sb.x + 1.f) * (sb.w - sb.y + 1.f);

        ull p = 0ull;
        #pragma unroll
        for (int j = 0; j < 4; j++) {
            int r = tid + j * 128;
            if (r >= N_BOX) continue;
            if (r == box) {
                g_labels[r] = cls;
                c1[j] = -1; c2[j] = -1; mmv[j] = MM_NONE;
            } else {
                float4 bb = bbj[j];
                float x1 = fmaxf(bb.x, sb.x);
                float y1 = fmaxf(bb.y, sb.y);
                float x2 = fminf(bb.z, sb.z);
                float y2 = fminf(bb.w, sb.w);
                float inter = fmaxf(x2 - x1 + 1.f, 0.f) * fmaxf(y2 - y1 + 1.f, 0.f);
                float area  = (bb.z - bb.x + 1.f) * (bb.w - bb.y + 1.f);
                float uni   = area + sarea - inter;
                if (inter / uni >= 0.5f) {
                    scl[j * C_CLS + cls] = 0.f;
                    if (cls < mmv[j]) mmv[j] = cls;
                    if (cls == c1[j]) {
                        if (c2[j] >= 0) { m1[j] = m2[j]; c1[j] = c2[j]; c2[j] = -1; }
                        else {
                            // rescan thread-local row for new top-2 (positives only)
                            float a1 = 0.f, a2 = 0.f;
                            int k1 = -1, k2 = -1;
                            const float* sr = &scl[j * C_CLS];
                            for (int c = 1; c < C_CLS; c++) {
                                float vv = sr[c];
                                if (vv > a1) { a2 = a1; k2 = k1; a1 = vv; k1 = c; }
                                else if (vv > a2) { a2 = vv; k2 = c; }
                            }
                            m1[j] = a1; c1[j] = k1;
                            m2[j] = a2; c2[j] = k2;
                        }
                    } else if (cls == c2[j]) {
                        c2[j] = -1;
                    }
                }
            }
            ull q; ROWPACK(j, r, q);
            if (q > p) p = q;
        }
        #pragma unroll
        for (int o = 16; o; o >>= 1) {
            ull q = __shfl_xor_sync(0xffffffffu, p, o);
            if (q > p) p = q;
        }
        if (lane == 0 && p) atomicMax(&s_sel[t + 1], p);
        __syncthreads();
    }
    #undef ROWPACK
}

// ---------------- final: edge_ctx = relu(fcb + tab[label]); preds ----------------
__global__ __launch_bounds__(128) void edge_kernel(float* __restrict__ out)
{
    int row = blockIdx.x, tid = threadIdx.x;
    int lab = g_labels[row];
    if (tid == 0) out[N_BOX * C_CLS + row] = (float)lab;
    const float* fb = g_fcb + (size_t)row * H_DIM;
    const float* tb = g_tab + (size_t)lab * H_DIM;
    float* o = out + N_BOX * C_CLS + N_BOX + (size_t)row * H_DIM;
    for (int c = tid; c < H_DIM; c += 128) o[c] = fmaxf(fb[c] + tb[c], 0.f);
}

// ---------------- launch ----------------
extern "C" void kernel_launch(void* const* d_in, const int* in_sizes, int n_in,
                              void* d_out, int out_size)
{
    const float* x        = (const float*)d_in[0];
    const float* logits   = (const float*)d_in[1];
    const float* pos      = (const float*)d_in[2];
    const float* boxes    = (const float*)d_in[3];
    const float* objw     = (const float*)d_in[4];
    const float* objw2    = (const float*)d_in[5];
    const float* w_pos1   = (const float*)d_in[6];
    const float* b_pos1   = (const float*)d_in[7];
    const float* bn_g     = (const float*)d_in[8];
    const float* bn_b     = (const float*)d_in[9];
    const float* bn_m     = (const float*)d_in[10];
    const float* bn_v     = (const float*)d_in[11];
    const float* w_pos2   = (const float*)d_in[12];
    const float* b_pos2   = (const float*)d_in[13];
    const float* w_lin    = (const float*)d_in[14];
    const float* b_lin    = (const float*)d_in[15];
    const float* w_out    = (const float*)d_in[16];
    const float* b_out    = (const float*)d_in[17];
    const float* w_fc     = (const float*)d_in[18];
    const float* b_fc     = (const float*)d_in[19];
    float* out = (float*)d_out;

    float* h1;
    cudaGetSymbolAddress((void**)&h1, g_h1);

    transpose_boxes<<<N_BOX, 160>>>(boxes);
    prep_kernel<<<N_BOX, 256>>>(logits, pos, objw, w_pos1, b_pos1,
                                bn_g, bn_b, bn_m, bn_v, w_pos2, b_pos2);
    h1_splitk_kernel<<<dim3(4, 25, NSPLIT), 128>>>(x, w_lin);
    reduce_h1_kernel<<<N_BOX, 512>>>(b_lin);
    sgemm_kernel<<<dim3(2, 25), 128>>>(h1, H_DIM, w_out, C_CLS, out, C_CLS,
                                       N_BOX, C_CLS, H_DIM, b_out);
    scores_kernel<<<N_BOX, 256>>>(out);
    fused_kernel<<<FUSED_GRID, 128>>>(x, w_fc, b_fc, objw2);
    edge_kernel<<<N_BOX, 128>>>(out);
}

// round 4
// speedup vs baseline: 1.1925x; 1.1925x over previous
#include <cuda_runtime.h>
#include <math.h>

typedef unsigned long long ull;

#define N_BOX 400
#define C_CLS 151
#define D_X   4096
#define E_EMB 200
#define H_DIM 512
#define P_POS 128
#define K_REP  4424
#define K_REP2 4224
#define TAIL_W 328          /* E_EMB + P_POS */
#define SC_LD  152          /* padded score row stride (float4-aligned) */
#define FNEG_INF (-3.402823466e38f)
#define MM_NONE (1<<30)

// ---------------- scratch ----------------
__device__ float  g_tail[N_BOX * TAIL_W];
__device__ float  g_h1  [N_BOX * H_DIM];
__device__ float  g_fcb [N_BOX * H_DIM];
__device__ float  g_tab [C_CLS * H_DIM];
__device__ float  g_scores[N_BOX * SC_LD];     // row-major padded, PRISTINE (never rewritten)
__device__ float4 g_rowinit[N_BOX];            // (m1, c1, m2, c2)
__device__ float  g_boxT[C_CLS * N_BOX * 4];   // boxT[cls][r] float4
__device__ int    g_labels[N_BOX];

// ---------------- f32x2 helpers ----------------
__device__ __forceinline__ void ffma2(ull& d, ull a, ull b) {
    asm("fma.rn.f32x2 %0, %1, %2, %0;" : "+l"(d) : "l"(a), "l"(b));
}
__device__ __forceinline__ ull pack2(float lo, float hi) {
    ull r;
    asm("mov.b64 %0, {%1, %2};" : "=l"(r) : "f"(lo), "f"(hi));
    return r;
}
__device__ __forceinline__ void unpack2(ull v, float& lo, float& hi) {
    asm("mov.b64 {%0, %1}, %2;" : "=f"(lo), "=f"(hi) : "l"(v));
}

__device__ __forceinline__ float warp_max(float v) {
    #pragma unroll
    for (int o = 16; o; o >>= 1) v = fmaxf(v, __shfl_xor_sync(0xffffffffu, v, o));
    return v;
}
__device__ __forceinline__ float warp_sum(float v) {
    #pragma unroll
    for (int o = 16; o; o >>= 1) v += __shfl_xor_sync(0xffffffffu, v, o);
    return v;
}
__device__ __forceinline__ ull warp_maxu64(ull v) {
    #pragma unroll
    for (int o = 16; o; o >>= 1) {
        ull q = __shfl_xor_sync(0xffffffffu, v, o);
        if (q > v) v = q;
    }
    return v;
}

// ---------------- boxes transpose ----------------
__global__ __launch_bounds__(160) void transpose_boxes(const float* __restrict__ boxes)
{
    int r = blockIdx.x, c = threadIdx.x;
    if (c < C_CLS) {
        float4 v = ((const float4*)boxes)[(size_t)r * C_CLS + c];
        ((float4*)g_boxT)[(size_t)c * N_BOX + r] = v;
    }
}

// ---------------- prep: obj_embed + pos_embed -> g_tail ----------------
__global__ __launch_bounds__(256) void prep_kernel(
    const float* __restrict__ logits,
    const float* __restrict__ pos, const float* __restrict__ obj_embed_w,
    const float* __restrict__ w_pos1, const float* __restrict__ b_pos1,
    const float* __restrict__ bn_g, const float* __restrict__ bn_b,
    const float* __restrict__ bn_m, const float* __restrict__ bn_v,
    const float* __restrict__ w_pos2, const float* __restrict__ b_pos2)
{
    int row = blockIdx.x, tid = threadIdx.x;
    __shared__ float sp[C_CLS];
    __shared__ float sh[32];
    __shared__ float sred[8];

    float lv = (tid < C_CLS) ? logits[row * C_CLS + tid] : FNEG_INF;
    float m = warp_max(lv);
    if ((tid & 31) == 0) sred[tid >> 5] = m;
    __syncthreads();
    float bm = sred[0];
    #pragma unroll
    for (int i = 1; i < 8; i++) bm = fmaxf(bm, sred[i]);
    float e = (tid < C_CLS) ? expf(lv - bm) : 0.f;
    float s = warp_sum(e);
    __syncthreads();
    if ((tid & 31) == 0) sred[tid >> 5] = s;
    __syncthreads();
    float bs = 0.f;
    #pragma unroll
    for (int i = 0; i < 8; i++) bs += sred[i];
    if (tid < C_CLS) sp[tid] = e / bs;

    if (tid < 32) {
        float acc = b_pos1[tid];
        #pragma unroll
        for (int k = 0; k < 9; k++) acc += pos[row * 9 + k] * w_pos1[k * 32 + tid];
        acc = (acc - bn_m[tid]) / sqrtf(bn_v[tid] + 1e-5f) * bn_g[tid] + bn_b[tid];
        sh[tid] = acc;
    }
    __syncthreads();

    if (tid < E_EMB) {
        float acc = 0.f;
        for (int k = 0; k < C_CLS; k++) acc += sp[k] * obj_embed_w[k * E_EMB + tid];
        g_tail[row * TAIL_W + tid] = acc;
    }
    if (tid < P_POS) {
        float acc = b_pos2[tid];
        #pragma unroll
        for (int k = 0; k < 32; k++) acc += sh[k] * w_pos2[k * P_POS + tid];
        g_tail[row * TAIL_W + E_EMB + tid] = fmaxf(acc, 0.f);
    }
}

// ============ generic 16x128 GEMM tile, 512 threads, f32x2, N fixed = 512 ============
// mode 0: A = [x | g_tail(full)]      (h1: K=4424)
// mode 1: A = plain (lda)             (tab: objw2, K=200)
// mode 2: A = [x | g_tail(pos part)]  (fcb: K=4224)
__device__ __forceinline__ void gemm16x128(
    const float* __restrict__ A, int lda, int mode,
    const float* __restrict__ x,
    const float* __restrict__ B,
    float* __restrict__ Cg,
    int M, int K, const float* __restrict__ bias,
    int mt, int nt, float (*As)[18], float (*Bs)[128])
{
    int tid = threadIdx.x;
    int row0 = mt * 16, col0 = nt * 128;
    int p = tid >> 7;         // 0..3
    int c = tid & 127;
    ull acc0 = 0ull, acc1 = 0ull;   // row pairs (2p,2p+1) and (2p+8,2p+9)

    for (int k0 = 0; k0 < K; k0 += 16) {
        if (tid < 256) {
            int k = tid & 15, mm = tid >> 4;
            int gr = row0 + mm, gk = k0 + k;
            float v = 0.f;
            if (gr < M && gk < K) {
                if (mode == 0)
                    v = (gk < D_X) ? x[(size_t)gr * D_X + gk]
                                   : g_tail[gr * TAIL_W + (gk - D_X)];
                else if (mode == 2)
                    v = (gk < D_X) ? x[(size_t)gr * D_X + gk]
                                   : g_tail[gr * TAIL_W + E_EMB + (gk - D_X)];
                else
                    v = A[(size_t)gr * lda + gk];
            }
            As[k][mm] = v;
        }
        {
            int k = tid >> 5, n = (tid & 31) << 2;
            int gk = k0 + k;
            float4 v = make_float4(0.f, 0.f, 0.f, 0.f);
            if (gk < K) v = *(const float4*)(B + (size_t)gk * H_DIM + col0 + n);
            *(float4*)&Bs[k][n] = v;
        }
        __syncthreads();
        #pragma unroll
        for (int k = 0; k < 16; k++) {
            ull a0 = *(const ull*)&As[k][2 * p];
            ull a1 = *(const ull*)&As[k][2 * p + 8];
            float b = Bs[k][c];
            ull bb = pack2(b, b);
            ffma2(acc0, a0, bb);
            ffma2(acc1, a1, bb);
        }
        __syncthreads();
    }
    int gn = col0 + c;
    float bs = bias ? bias[gn] : 0.f;
    float v00, v01, v10, v11;
    unpack2(acc0, v00, v01);
    unpack2(acc1, v10, v11);
    int r0 = row0 + 2 * p;
    int r1 = row0 + 2 * p + 8;
    if (r0 < M)     Cg[(size_t)r0 * H_DIM + gn] = v00 + bs;
    if (r0 + 1 < M) Cg[(size_t)(r0 + 1) * H_DIM + gn] = v01 + bs;
    if (r1 < M)     Cg[(size_t)r1 * H_DIM + gn] = v10 + bs;
    if (r1 + 1 < M) Cg[(size_t)(r1 + 1) * H_DIM + gn] = v11 + bs;
}

// ---------------- h1 = [x|tail] @ w_lin + b_lin ----------------
__global__ __launch_bounds__(512) void h1_kernel(
    const float* __restrict__ x, const float* __restrict__ wlin,
    const float* __restrict__ b_lin)
{
    __shared__ __align__(16) float As[16][18];
    __shared__ __align__(16) float Bs[16][128];
    gemm16x128(0, 0, 0, x, wlin, g_h1, N_BOX, K_REP, b_lin,
               blockIdx.y, blockIdx.x, As, Bs);
}

// ---------------- dists SGEMM (scalar, small): out = h1 @ w_out + b_out ----------------
__global__ __launch_bounds__(128) void sgemm_kernel(
    const float* __restrict__ A, int lda,
    const float* __restrict__ B, int ldb,
    float* __restrict__ C, int ldc,
    int M, int N, int K,
    const float* __restrict__ bias)
{
    __shared__ float As[16][17];
    __shared__ float Bs[16][128];
    int tid = threadIdx.x;
    int tx = tid & 31, ty = tid >> 5;
    int row0 = blockIdx.y * 16;
    int col0 = blockIdx.x * 128;
    float acc[4][4];
    #pragma unroll
    for (int i = 0; i < 4; i++)
        #pragma unroll
        for (int j = 0; j < 4; j++) acc[i][j] = 0.f;

    for (int k0 = 0; k0 < K; k0 += 16) {
        #pragma unroll
        for (int i = 0; i < 2; i++) {
            int l = tid * 2 + i;
            int m = l >> 4, k = l & 15;
            int gr = row0 + m, gk = k0 + k;
            As[k][m] = (gr < M && gk < K) ? A[(size_t)gr * lda + gk] : 0.f;
        }
        #pragma unroll
        for (int i = 0; i < 4; i++) {
            int f = tid + i * 128;
            int k = f >> 5, n = (f & 31) << 2;
            int gk = k0 + k, gn = col0 + n;
            float4 v = make_float4(0.f, 0.f, 0.f, 0.f);
            if (gk < K) {
                float t0 = (gn + 0 < N) ? B[(size_t)gk * ldb + gn + 0] : 0.f;
                float t1 = (gn + 1 < N) ? B[(size_t)gk * ldb + gn + 1] : 0.f;
                float t2 = (gn + 2 < N) ? B[(size_t)gk * ldb + gn + 2] : 0.f;
                float t3 = (gn + 3 < N) ? B[(size_t)gk * ldb + gn + 3] : 0.f;
                v = make_float4(t0, t1, t2, t3);
            }
            *(float4*)&Bs[k][n] = v;
        }
        __syncthreads();
        #pragma unroll
        for (int k = 0; k < 16; k++) {
            float a0 = As[k][ty * 4 + 0];
            float a1 = As[k][ty * 4 + 1];
            float a2 = As[k][ty * 4 + 2];
            float a3 = As[k][ty * 4 + 3];
            float4 bv = *(float4*)&Bs[k][tx * 4];
            acc[0][0] += a0 * bv.x; acc[0][1] += a0 * bv.y; acc[0][2] += a0 * bv.z; acc[0][3] += a0 * bv.w;
            acc[1][0] += a1 * bv.x; acc[1][1] += a1 * bv.y; acc[1][2] += a1 * bv.z; acc[1][3] += a1 * bv.w;
            acc[2][0] += a2 * bv.x; acc[2][1] += a2 * bv.y; acc[2][2] += a2 * bv.z; acc[2][3] += a2 * bv.w;
            acc[3][0] += a3 * bv.x; acc[3][1] += a3 * bv.y; acc[3][2] += a3 * bv.z; acc[3][3] += a3 * bv.w;
        }
        __syncthreads();
    }
    #pragma unroll
    for (int i = 0; i < 4; i++) {
        int gr = row0 + ty * 4 + i;
        if (gr >= M) continue;
        #pragma unroll
        for (int j = 0; j < 4; j++) {
            int gn = col0 + tx * 4 + j;
            if (gn >= N) continue;
            C[(size_t)gr * ldc + gn] = acc[i][j] + bias[gn];
        }
    }
}

// ---------------- scores: softmax (row-major padded) + per-row top-2 init ----------------
__global__ __launch_bounds__(256) void scores_kernel(const float* __restrict__ obj_dists)
{
    int row = blockIdx.x, tid = threadIdx.x;
    __shared__ float sred[8];
    __shared__ float4 stop[8];

    float lv = (tid < C_CLS) ? obj_dists[row * C_CLS + tid] : FNEG_INF;
    float m = warp_max(lv);
    if ((tid & 31) == 0) sred[tid >> 5] = m;
    __syncthreads();
    float bm = sred[0];
    #pragma unroll
    for (int i = 1; i < 8; i++) bm = fmaxf(bm, sred[i]);
    float e = (tid < C_CLS) ? expf(lv - bm) : 0.f;
    float s = warp_sum(e);
    __syncthreads();
    if ((tid & 31) == 0) sred[tid >> 5] = s;
    __syncthreads();
    float bs = 0.f;
    #pragma unroll
    for (int i = 0; i < 8; i++) bs += sred[i];

    float v = (tid == 0) ? -1.f : e / bs;
    if (tid < C_CLS) g_scores[row * SC_LD + tid] = v;
    if (tid == C_CLS) g_scores[row * SC_LD + C_CLS] = -1.f;  // padding slot

    // top-2 over positive entries (cols 1..150), ties -> smaller col
    float tv = (tid > 0 && tid < C_CLS) ? v : -1e30f;
    float m1 = tv, m2 = -1e30f;
    int c1 = tid, c2 = 0x7fff;
    #pragma unroll
    for (int o = 16; o; o >>= 1) {
        float om1 = __shfl_xor_sync(0xffffffffu, m1, o);
        float om2 = __shfl_xor_sync(0xffffffffu, m2, o);
        int   oc1 = __shfl_xor_sync(0xffffffffu, c1, o);
        int   oc2 = __shfl_xor_sync(0xffffffffu, c2, o);
        if (om1 > m1 || (om1 == m1 && oc1 < c1)) { m2 = m1; c2 = c1; m1 = om1; c1 = oc1; }
        else if (om1 > m2 || (om1 == m2 && oc1 < c2)) { m2 = om1; c2 = oc1; }
        if (om2 > m2 || (om2 == m2 && oc2 < c2)) { m2 = om2; c2 = oc2; }
    }
    if ((tid & 31) == 0) stop[tid >> 5] = make_float4(m1, __int_as_float(c1), m2, __int_as_float(c2));
    __syncthreads();
    if (tid == 0) {
        float4 a = stop[0];
        float rm1 = a.x, rm2 = a.z;
        int rc1 = __float_as_int(a.y), rc2 = __float_as_int(a.w);
        for (int w = 1; w < 8; w++) {
            float4 b = stop[w];
            float wm1 = b.x, wm2 = b.z;
            int wc1 = __float_as_int(b.y), wc2 = __float_as_int(b.w);
            if (wm1 > rm1 || (wm1 == rm1 && wc1 < rc1)) { rm2 = rm1; rc2 = rc1; rm1 = wm1; rc1 = wc1; }
            else if (wm1 > rm2 || (wm1 == rm2 && wc1 < rc2)) { rm2 = wm1; rc2 = wc1; }
            if (wm2 > rm2 || (wm2 == rm2 && wc2 < rc2)) { rm2 = wm2; rc2 = wc2; }
        }
        g_rowinit[row] = make_float4(rm1, __int_as_float(rc1), rm2, __int_as_float(rc2));
    }
}

// ============== fused: block0 greedy, blocks 1..140 fcb/tab GEMM tiles ==============
#define FCB_BLOCKS 100   /* 25 mt x 4 nt */
#define TAB_BLOCKS 40    /* 10 mt x 4 nt */
#define FUSED_GRID (1 + FCB_BLOCKS + TAB_BLOCKS)

__global__ __launch_bounds__(512, 1) void fused_kernel(
    const float* __restrict__ x,
    const float* __restrict__ w_fc, const float* __restrict__ b_fc,
    const float* __restrict__ objw2)
{
    __shared__ __align__(16) float As[16][18];
    __shared__ __align__(16) float Bs[16][128];
    __shared__ ull s_warp[2][16];

    int bid = blockIdx.x;
    int tid = threadIdx.x;

    if (bid >= 1 && bid < 1 + FCB_BLOCKS) {
        int bi = bid - 1;
        gemm16x128(0, 0, 2, x, w_fc, g_fcb, N_BOX, K_REP2, b_fc,
                   bi >> 2, bi & 3, As, Bs);
        return;
    }
    if (bid >= 1 + FCB_BLOCKS) {
        int bj = bid - 1 - FCB_BLOCKS;
        gemm16x128(objw2, E_EMB, 1, x, w_fc + (size_t)K_REP2 * H_DIM, g_tab,
                   C_CLS, E_EMB, 0, bj >> 2, bj & 3, As, Bs);
        return;
    }

    // ================= block 0: greedy NMS, 512 threads, 1 row/thread =================
    int lane = tid & 31, wid = tid >> 5;
    int r = tid;
    bool active = (r < N_BOX);

    float m1 = 0.f, m2 = 0.f;
    int   c1 = -1, c2 = -1, mmv = MM_NONE;
    unsigned mk0 = 0, mk1 = 0, mk2 = 0, mk3 = 0, mk4 = (1u << 23);  // bit 151 = padding

    if (active) {
        float4 ri = g_rowinit[r];
        m1 = ri.x; c1 = __float_as_int(ri.y);
        m2 = ri.z; c2 = __float_as_int(ri.w);
        g_labels[r] = 0;
    }

    #define ROWPACK(out) do {                                                  \
        float _v; int _sc;                                                     \
        if (c1 >= 0) { _v = m1; _sc = c1; }                                    \
        else if (mmv < MM_NONE) { _v = 0.f; _sc = mmv; }                       \
        else { _v = -1.f; _sc = 0; }                                           \
        out = ((ull)__float_as_uint(_v + 2.f) << 17)                           \
            | ((ull)(511 - r) << 8) | (ull)_sc;                                \
    } while (0)

    {
        ull q = 0ull;
        if (active) ROWPACK(q);
        q = warp_maxu64(q);
        if (lane == 0) s_warp[0][wid] = q;
        __syncthreads();
    }

    for (int t = 0; t < N_BOX; t++) {
        int par = t & 1;
        // every warp redundantly reduces the 16 partials -> selection
        ull sel = (lane < 16) ? s_warp[par][lane] : 0ull;
        sel = warp_maxu64(sel);
        int box = 511 - (int)((sel >> 8) & 0x1FF);
        int cls = (int)(sel & 0xFF);

        if (active) {
            const float4* bt = (const float4*)g_boxT + (size_t)cls * N_BOX;
            if (r == box) {
                g_labels[r] = cls;
                m1 = 0.f; m2 = 0.f; c1 = -1; c2 = -1; mmv = MM_NONE;
                mk0 = 0; mk1 = 0; mk2 = 0; mk3 = 0; mk4 = (1u << 23);
            } else {
                float4 sb = bt[box];
                float4 bb = bt[r];
                float x1 = fmaxf(bb.x, sb.x);
                float y1 = fmaxf(bb.y, sb.y);
                float x2 = fminf(bb.z, sb.z);
                float y2 = fminf(bb.w, sb.w);
                float inter = fmaxf(x2 - x1 + 1.f, 0.f) * fmaxf(y2 - y1 + 1.f, 0.f);
                float area  = (bb.z - bb.x + 1.f) * (bb.w - bb.y + 1.f);
                float sarea = (sb.z - sb.x + 1.f) * (sb.w - sb.y + 1.f);
                float uni   = area + sarea - inter;
                if (inter / uni >= 0.5f) {
                    int w = cls >> 5;
                    unsigned bit = 1u << (cls & 31);
                    unsigned cur = (w == 0) ? mk0 : (w == 1) ? mk1 : (w == 2) ? mk2
                                 : (w == 3) ? mk3 : mk4;
                    if (!(cur & bit)) {
                        if (w == 0) mk0 |= bit; else if (w == 1) mk1 |= bit;
                        else if (w == 2) mk2 |= bit; else if (w == 3) mk3 |= bit;
                        else mk4 |= bit;
                        if (cls < mmv) mmv = cls;
                        if (cls == c1) {
                            if (c2 >= 0) { m1 = m2; c1 = c2; c2 = -1; }
                            else {
                                // full rescan over pristine scores, skipping masked bits
                                float a1 = 0.f, a2 = 0.f;
                                int k1 = -1, k2 = -1;
                                const float4* rp = (const float4*)(g_scores + r * SC_LD);
                                #pragma unroll
                                for (int qq = 0; qq < 38; qq++) {
                                    float4 v4 = rp[qq];
                                    int cb = qq * 4;
                                    #pragma unroll
                                    for (int ee = 0; ee < 4; ee++) {
                                        int cc = cb + ee;
                                        float vv = (ee == 0) ? v4.x : (ee == 1) ? v4.y
                                                 : (ee == 2) ? v4.z : v4.w;
                                        int ww = cc >> 5;
                                        unsigned mw = (ww == 0) ? mk0 : (ww == 1) ? mk1
                                                    : (ww == 2) ? mk2 : (ww == 3) ? mk3 : mk4;
                                        bool ok = !((mw >> (cc & 31)) & 1u);
                                        if (ok && vv > a1) { a2 = a1; k2 = k1; a1 = vv; k1 = cc; }
                                        else if (ok && vv > a2) { a2 = vv; k2 = cc; }
                                    }
                                }
                                m1 = a1; c1 = k1; m2 = a2; c2 = k2;
                            }
                        } else if (cls == c2) {
                            c2 = -1;
                        }
                    }
                }
            }
        }

        ull q = 0ull;
        if (active) ROWPACK(q);
        q = warp_maxu64(q);
        if (lane == 0) s_warp[par ^ 1][wid] = q;
        __syncthreads();
    }
    #undef ROWPACK
}

// ---------------- final: edge_ctx = relu(fcb + tab[label]); preds ----------------
__global__ __launch_bounds__(128) void edge_kernel(float* __restrict__ out)
{
    int row = blockIdx.x, tid = threadIdx.x;
    int lab = g_labels[row];
    if (tid == 0) out[N_BOX * C_CLS + row] = (float)lab;
    const float* fb = g_fcb + (size_t)row * H_DIM;
    const float* tb = g_tab + (size_t)lab * H_DIM;
    float* o = out + N_BOX * C_CLS + N_BOX + (size_t)row * H_DIM;
    for (int c = tid; c < H_DIM; c += 128) o[c] = fmaxf(fb[c] + tb[c], 0.f);
}

// ---------------- launch ----------------
extern "C" void kernel_launch(void* const* d_in, const int* in_sizes, int n_in,
                              void* d_out, int out_size)
{
    const float* x        = (const float*)d_in[0];
    const float* logits   = (const float*)d_in[1];
    const float* pos      = (const float*)d_in[2];
    const float* boxes    = (const float*)d_in[3];
    const float* objw     = (const float*)d_in[4];
    const float* objw2    = (const float*)d_in[5];
    const float* w_pos1   = (const float*)d_in[6];
    const float* b_pos1   = (const float*)d_in[7];
    const float* bn_g     = (const float*)d_in[8];
    const float* bn_b     = (const float*)d_in[9];
    const float* bn_m     = (const float*)d_in[10];
    const float* bn_v     = (const float*)d_in[11];
    const float* w_pos2   = (const float*)d_in[12];
    const float* b_pos2   = (const float*)d_in[13];
    const float* w_lin    = (const float*)d_in[14];
    const float* b_lin    = (const float*)d_in[15];
    const float* w_out    = (const float*)d_in[16];
    const float* b_out    = (const float*)d_in[17];
    const float* w_fc     = (const float*)d_in[18];
    const float* b_fc     = (const float*)d_in[19];
    float* out = (float*)d_out;

    float* h1;
    cudaGetSymbolAddress((void**)&h1, g_h1);

    transpose_boxes<<<N_BOX, 160>>>(boxes);
    prep_kernel<<<N_BOX, 256>>>(logits, pos, objw, w_pos1, b_pos1,
                                bn_g, bn_b, bn_m, bn_v, w_pos2, b_pos2);
    h1_kernel<<<dim3(4, 25), 512>>>(x, w_lin, b_lin);
    sgemm_kernel<<<dim3(2, 25), 128>>>(h1, H_DIM, w_out, C_CLS, out, C_CLS,
                                       N_BOX, C_CLS, H_DIM, b_out);
    scores_kernel<<<N_BOX, 256>>>(out);
    fused_kernel<<<FUSED_GRID, 512>>>(x, w_fc, b_fc, objw2);
    edge_kernel<<<N_BOX, 128>>>(out);
}